// round 14
// baseline (speedup 1.0000x reference)
#include <cuda_runtime.h>

// OrthonormalWaveletRegularization: L=32 -> scalar. One warp, all-fp32.
// R13 (terminal): R10 structure with loads hoisted to the top and the
// load-independent power chain scheduled into the LDG shadow.
// 32 chains = 32 lanes (lag k=0..15, lag0 == dot(h,h); moments p=1..16),
// Sum(h) butterfly overlapped with STS, one syncwarp, LDS.128 transpose,
// 5-SHFL final butterfly, l1 folded at lane 31.
//
// Session verdict: kernel dur stable 3.6-4.0us across 7 variants; wall is
// bimodal 4.576/6.88us UNCORRELATED with source (same bytes measured both).
// Overhead-bound (T_ovh + L2-warm LDG + ~500 cyc work at idle clock);
// all roofline resources ~0%. No optimization headroom remains.

#define SQRT2F 1.41421356237309504880f

__global__ void owr_kernel(const float* __restrict__ h,
                           const float* __restrict__ g,
                           float* __restrict__ out) {
    const int t = threadIdx.x;                       // lane = element index r
    __shared__ __align__(16) float s[32][36];        // 32 chains, stride 36

    // --- issue both loads first (MLP=2), fill the shadow with t-only math ---
    const float hv = h[t];
    const float gv = g[t];

    // power chain depends only on t: executes under the LDG latency
    const float r1 = (float)t;
    const float r2 = r1 * r1;
    const float r4 = r2 * r2;
    const float r8 = r4 * r4;
    float w[16];
    w[0]  = 1.0f;        w[1]  = r1;          w[2]  = r2;          w[3]  = r2 * r1;
    w[4]  = r4;          w[5]  = r4 * r1;     w[6]  = r4 * r2;     w[7]  = w[6] * r1;
    w[8]  = r8;          w[9]  = r8 * r1;     w[10] = r8 * r2;     w[11] = w[10] * r1;
    w[12] = r8 * r4;     w[13] = w[12] * r1;  w[14] = w[12] * r2;  w[15] = w[14] * r1;

    // --- lag chains k=0..15 (rows 0..15): h[r]*h[r+2k]; k=0 gives h^2 ---
    #pragma unroll
    for (int k = 0; k <= 15; ++k) {
        const int d = 2 * k;
        const float hs = __shfl_down_sync(0xFFFFFFFFu, hv, d);
        s[k][t] = (t + d < 32) ? hv * hs : 0.0f;
    }

    // --- moment chains p=1..16 (rows 16..31): r^(p-1)*g[r] ---
    #pragma unroll
    for (int p = 1; p <= 16; ++p)
        s[15 + p][t] = w[p - 1] * gv;

    // --- Sum(h) butterfly: overlaps the STS drain above ---
    float s_h = hv;
    #pragma unroll
    for (int o = 16; o > 0; o >>= 1)
        s_h += __shfl_xor_sync(0xFFFFFFFFu, s_h, o);

    __syncwarp();

    // --- transpose: lane j tree-sums chain j with LDS.128 reads ---
    float ssum;
    {
        const float4* row = (const float4*)s[t];
        float x[8];
        #pragma unroll
        for (int i = 0; i < 8; ++i) {
            const float4 q = row[i];
            x[i] = (q.x + q.y) + (q.z + q.w);
        }
        ssum = ((x[0] + x[1]) + (x[2] + x[3])) + ((x[4] + x[5]) + (x[6] + x[7]));
    }

    // --- per-lane contribution ---
    float contrib;
    if (t == 0) {
        const float e3 = ssum - 1.0f;                                // lag0 = dot(h,h)
        contrib = e3 * e3;                                           // l3
    } else if (t <= 15) {
        contrib = ssum * ssum;                                       // l4 term (lag t)
    } else {
        const int p = t - 15;                                        // 1..16
        if (p == 1) {
            contrib = 1.5f * ssum * ssum;                            // l2 + p=1 l5 term
        } else {
            const float norm = SQRT2F * __int_as_float((127 - p) << 23); // sqrt2*2^-p
            const float m = ssum * norm;
            contrib = m * m;                                         // l5 term
        }
        if (t == 31) {
            const float e1 = s_h - SQRT2F;
            contrib += e1 * e1;                                      // l1
        }
    }

    // --- final 5-stage butterfly, lane 0 stores ---
    #pragma unroll
    for (int o = 16; o > 0; o >>= 1)
        contrib += __shfl_xor_sync(0xFFFFFFFFu, contrib, o);

    if (t == 0)
        out[0] = contrib;
}

extern "C" void kernel_launch(void* const* d_in, const int* in_sizes, int n_in,
                              void* d_out, int out_size) {
    const float* h = (const float*)d_in[0];
    const float* g = (const float*)d_in[1];
    float* out = (float*)d_out;
    owr_kernel<<<1, 32>>>(h, g, out);
}

// round 15
// speedup vs baseline: 1.0047x; 1.0047x over previous
#include <cuda_runtime.h>

// OrthonormalWaveletRegularization: L=32 -> scalar. One warp, all-fp32.
// FINAL (byte-exact R10, session-best wall 4.576us / kernel 3.68us).
//
// Design: 32 smem chains = 32 lanes. Chains 0..15 are even-lag autocorr
// h[r]*h[r+2k] (lag0 IS dot(h,h) -> l3). Chains 16..31 are moment rows
// r^(p-1)*g[r] (p=1 row doubles as sum(g) -> l2 via the 1.5x fold).
// Sum(h) runs as a 5-SHFL butterfly overlapped with the STS drain (-> l1,
// folded at lane 31). One syncwarp; conflict-free stride-36 LDS.128
// transpose; per-lane square/scale with exact 2^-p bit-built norms; final
// 5-SHFL butterfly; single STG.
//
// Session evidence (14 rounds): baseline 96.6us (fp64 pow-bound) -> 8.9
// (const table) -> 4.58 (shuffle/transpose family). Kernel dur stable
// 3.6-4.5us across 7 structural variants incl. byte-identical resubmits;
// wall bimodal 4.576/6.88us by container clock mode, uncorrelated with
// source. All roofline resources ~0%: overhead-bound, no headroom.

#define SQRT2F 1.41421356237309504880f

__global__ void owr_kernel(const float* __restrict__ h,
                           const float* __restrict__ g,
                           float* __restrict__ out) {
    const int t = threadIdx.x;                       // lane = element index r
    __shared__ __align__(16) float s[32][36];        // 32 chains, stride 36

    const float hv = h[t];
    const float gv = g[t];

    // --- moment chains p=1..16 (rows 16..31): r^(p-1)*g[r], log-depth powers ---
    {
        const float r1 = (float)t;
        const float r2 = r1 * r1;
        const float r4 = r2 * r2;
        const float r8 = r4 * r4;
        float w[16];
        w[0]  = 1.0f;        w[1]  = r1;          w[2]  = r2;          w[3]  = r2 * r1;
        w[4]  = r4;          w[5]  = r4 * r1;     w[6]  = r4 * r2;     w[7]  = w[6] * r1;
        w[8]  = r8;          w[9]  = r8 * r1;     w[10] = r8 * r2;     w[11] = w[10] * r1;
        w[12] = r8 * r4;     w[13] = w[12] * r1;  w[14] = w[12] * r2;  w[15] = w[14] * r1;
        #pragma unroll
        for (int p = 1; p <= 16; ++p)
            s[15 + p][t] = w[p - 1] * gv;
    }

    // --- lag chains k=0..15 (rows 0..15): h[r]*h[r+2k]; k=0 gives h^2 ---
    #pragma unroll
    for (int k = 0; k <= 15; ++k) {
        const int d = 2 * k;
        const float hs = __shfl_down_sync(0xFFFFFFFFu, hv, d);
        s[k][t] = (t + d < 32) ? hv * hs : 0.0f;
    }

    // --- Sum(h) butterfly: overlaps the STS drain above ---
    float s_h = hv;
    #pragma unroll
    for (int o = 16; o > 0; o >>= 1)
        s_h += __shfl_xor_sync(0xFFFFFFFFu, s_h, o);

    __syncwarp();

    // --- transpose: lane j tree-sums chain j with LDS.128 reads ---
    float ssum;
    {
        const float4* row = (const float4*)s[t];
        float x[8];
        #pragma unroll
        for (int i = 0; i < 8; ++i) {
            const float4 q = row[i];
            x[i] = (q.x + q.y) + (q.z + q.w);
        }
        ssum = ((x[0] + x[1]) + (x[2] + x[3])) + ((x[4] + x[5]) + (x[6] + x[7]));
    }

    // --- per-lane contribution ---
    float contrib;
    if (t == 0) {
        const float e3 = ssum - 1.0f;                                // lag0 = dot(h,h)
        contrib = e3 * e3;                                           // l3
    } else if (t <= 15) {
        contrib = ssum * ssum;                                       // l4 term (lag t)
    } else {
        const int p = t - 15;                                        // 1..16
        if (p == 1) {
            contrib = 1.5f * ssum * ssum;                            // l2 + p=1 l5 term
        } else {
            const float norm = SQRT2F * __int_as_float((127 - p) << 23); // sqrt2*2^-p
            const float m = ssum * norm;
            contrib = m * m;                                         // l5 term
        }
        if (t == 31) {
            const float e1 = s_h - SQRT2F;
            contrib += e1 * e1;                                      // l1
        }
    }

    // --- final 5-stage butterfly, lane 0 stores ---
    #pragma unroll
    for (int o = 16; o > 0; o >>= 1)
        contrib += __shfl_xor_sync(0xFFFFFFFFu, contrib, o);

    if (t == 0)
        out[0] = contrib;
}

extern "C" void kernel_launch(void* const* d_in, const int* in_sizes, int n_in,
                              void* d_out, int out_size) {
    const float* h = (const float*)d_in[0];
    const float* g = (const float*)d_in[1];
    float* out = (float*)d_out;
    owr_kernel<<<1, 32>>>(h, g, out);
}